// round 10
// baseline (speedup 1.0000x reference)
#include <cuda_runtime.h>
#include <cuda_bf16.h>
#include <cstdint>

// Problem constants
#define BATCH 4
#define NY 16384
#define NX 4096
#define CY 128
#define CX 256
#define DIMF 384       // CY + CX
#define C1 512
#define C2 256
#define C3 128
#define MTOT (BATCH*NY)   // 65536
#define IEPS 1e-8f
#define BN_EPS 1e-5f

// ---------------- scratch (device globals; no runtime alloc) ----------------
__device__ float g_feat[(size_t)MTOT * DIMF];
__device__ float g_z1[(size_t)MTOT * C1];
__device__ float g_z2[(size_t)MTOT * C2];
__device__ float g_z3[(size_t)MTOT * C3];
__device__ float g_red[1792];
__device__ float g_aff[1792];
// pre-split weights (bf16x2 words, row-major [N][K/2])
#define W1W (C1 * DIMF / 2)
#define W2W (C2 * C1 / 2)
#define W3W (C3 * C2 / 2)
__device__ uint32_t g_w1h[W1W], g_w1l[W1W];
__device__ uint32_t g_w2h[W2W], g_w2l[W2W];
__device__ uint32_t g_w3h[W3W], g_w3l[W3W];

// pack two floats to bf16x2 (a -> low half, b -> high half)
__device__ __forceinline__ uint32_t cvt2bf(float lo, float hi) {
    uint32_t r;
    asm("cvt.rn.bf16x2.f32 %0, %1, %2;" : "=r"(r) : "f"(hi), "f"(lo));
    return r;
}
__device__ __forceinline__ void split2(float a, float b, uint32_t& h, uint32_t& l) {
    h = cvt2bf(a, b);
    float h0 = __uint_as_float(h << 16);
    float h1 = __uint_as_float(h & 0xffff0000u);
    l = cvt2bf(a - h0, b - h1);
}

// m16n8k16 BF16 mma
__device__ __forceinline__ void mma16(float* c, const uint32_t* a, const uint32_t* b) {
    asm volatile(
        "mma.sync.aligned.m16n8k16.row.col.f32.bf16.bf16.f32 "
        "{%0,%1,%2,%3}, {%4,%5,%6,%7}, {%8,%9}, {%0,%1,%2,%3};"
        : "+f"(c[0]), "+f"(c[1]), "+f"(c[2]), "+f"(c[3])
        : "r"(a[0]), "r"(a[1]), "r"(a[2]), "r"(a[3]),
          "r"(b[0]), "r"(b[1]));
}
#define LDSM4(r0, r1, r2, r3, addr) \
    asm volatile("ldmatrix.sync.aligned.m8n8.x4.shared.b16 {%0,%1,%2,%3}, [%4];" \
        : "=r"(r0), "=r"(r1), "=r"(r2), "=r"(r3) : "r"(addr))
#define CPASYNC16(dst, src) \
    asm volatile("cp.async.cg.shared.global [%0], [%1], 16;" :: "r"(dst), "l"(src))
#define CPCOMMIT()  asm volatile("cp.async.commit_group;" ::: "memory")
#define CPWAIT0()   asm volatile("cp.async.wait_group 0;" ::: "memory")

__device__ __forceinline__ uint32_t smem_u32(const void* p) {
    uint32_t a;
    asm("{ .reg .u64 t; cvta.to.shared.u64 t, %1; cvt.u32.u64 %0, t; }" : "=r"(a) : "l"(p));
    return a;
}

// ---------------- combined weight split prep (one launch) ----------------
__global__ void split_w_all_kernel(const float* __restrict__ W1f, const float* __restrict__ W2f,
                                   const float* __restrict__ W3f,
                                   uint32_t* __restrict__ w1h, uint32_t* __restrict__ w1l,
                                   uint32_t* __restrict__ w2h, uint32_t* __restrict__ w2l,
                                   uint32_t* __restrict__ w3h, uint32_t* __restrict__ w3l)
{
    int i = blockIdx.x * blockDim.x + threadIdx.x;
    const float* W; uint32_t *H, *L; int idx;
    if (i < W1W) { W = W1f; H = w1h; L = w1l; idx = i; }
    else if (i < W1W + W2W) { W = W2f; H = w2h; L = w2l; idx = i - W1W; }
    else if (i < W1W + W2W + W3W) { W = W3f; H = w3h; L = w3l; idx = i - W1W - W2W; }
    else return;
    uint32_t h, l;
    split2(W[2 * idx], W[2 * idx + 1], h, l);
    H[idx] = h; L[idx] = l;
}

// ---------------- KNN + interpolation + concat (exact fp32 op-tree) ----------------
#define NXC 2048
__global__ __launch_bounds__(256)
void knn_interp_kernel(const float* __restrict__ yp, const float* __restrict__ yf,
                       const float* __restrict__ xp, const float* __restrict__ xf,
                       float* __restrict__ feat)
{
    __shared__ float4 s_pt[NXC];
    int b = blockIdx.y;
    int tid = threadIdx.x;
    int n = blockIdx.x * 256 + tid;
    int m = b * NY + n;

    const float* xpb = xp + (size_t)b * NX * 3;
    float px = yp[(size_t)m * 3 + 0];
    float py = yp[(size_t)m * 3 + 1];
    float pz = yp[(size_t)m * 3 + 2];
    float psq = __fadd_rn(__fadd_rn(__fmul_rn(px, px), __fmul_rn(py, py)),
                          __fmul_rn(pz, pz));

    float d0 = 3.4e38f, d1 = 3.4e38f, d2 = 3.4e38f;
    int i0 = 0, i1 = 0, i2 = 0;

    for (int ch = 0; ch < NX; ch += NXC) {
        __syncthreads();
        for (int j = tid; j < NXC; j += 256) {
            const float* xq = xpb + 3 * (size_t)(ch + j);
            float x = xq[0], y = xq[1], z = xq[2];
            float xsq = __fadd_rn(__fadd_rn(__fmul_rn(x, x), __fmul_rn(y, y)),
                                  __fmul_rn(z, z));
            s_pt[j] = make_float4(x, y, z, xsq);
        }
        __syncthreads();
        #pragma unroll 8
        for (int j = 0; j < NXC; j++) {
            float4 q = s_pt[j];
            float dot = __fmaf_rn(pz, q.z, __fmaf_rn(py, q.y, __fmul_rn(px, q.x)));
            float d = __fsub_rn(__fadd_rn(psq, q.w), __fmul_rn(2.0f, dot));
            if (d < d2) {
                int jj = ch + j;
                if (d < d1) {
                    d2 = d1; i2 = i1;
                    if (d < d0) { d1 = d0; i1 = i0; d0 = d; i0 = jj; }
                    else        { d1 = d;  i1 = jj; }
                } else { d2 = d; i2 = jj; }
            }
        }
    }

    float w0 = 1.0f / (d0 + IEPS);
    float w1 = 1.0f / (d1 + IEPS);
    float w2 = 1.0f / (d2 + IEPS);
    float ws = 1.0f / (w0 + w1 + w2);
    w0 *= ws; w1 *= ws; w2 *= ws;

    int lane = tid & 31;
    const float* xfb = xf + (size_t)b * NX * CX;
    unsigned mask = 0xffffffffu;
    for (int s = 0; s < 32; s++) {
        int   j0 = __shfl_sync(mask, i0, s);
        int   j1 = __shfl_sync(mask, i1, s);
        int   j2 = __shfl_sync(mask, i2, s);
        float a0 = __shfl_sync(mask, w0, s);
        float a1 = __shfl_sync(mask, w1, s);
        float a2 = __shfl_sync(mask, w2, s);
        int ms = m - lane + s;
        float* frow = feat + (size_t)ms * DIMF;
        const float4* ysrc = (const float4*)(yf + (size_t)ms * CY);
        ((float4*)frow)[lane] = ysrc[lane];
        const float4* r0 = (const float4*)(xfb + (size_t)j0 * CX);
        const float4* r1 = (const float4*)(xfb + (size_t)j1 * CX);
        const float4* r2 = (const float4*)(xfb + (size_t)j2 * CX);
        float4* dst = (float4*)(frow + CY);
        #pragma unroll
        for (int h = 0; h < 2; h++) {
            int c4 = h * 32 + lane;
            float4 v0 = r0[c4], v1 = r1[c4], v2 = r2[c4];
            float4 o;
            o.x = a0 * v0.x + a1 * v1.x + a2 * v2.x;
            o.y = a0 * v0.y + a1 * v1.y + a2 * v2.y;
            o.z = a0 * v0.z + a1 * v1.z + a2 * v2.z;
            o.w = a0 * v0.w + a1 * v1.w + a2 * v2.w;
            dst[c4] = o;
        }
    }
}

// ---------------- hybrid GEMM: tensor-path (3xBF16 HMMA) + FFMA-path (exact fp32) -------
// Tiles 128x128x16, grid (N/128, M/128). m-tiles with y%3==2 use the fp32 FFMA pipe,
// the rest use the bf16 tensor pipe. 2 CTAs/SM -> both pipes busy per SM.
#define SROW_W 12
#define A_W   (128 * SROW_W)             // 1536 words per operand array
#define OFF_AL A_W
#define OFF_BH (2 * A_W)
#define OFF_BL (3 * A_W)
#define BUFF_W (4 * A_W)                 // 6144 words per buffer
#define GEMM_SMEM (2 * BUFF_W * 4)       // 49152 bytes

template<bool NORM>
__global__ __launch_bounds__(256, 2)
void hybrid_gemm_kernel(const float* __restrict__ Afp,
                        const uint32_t* __restrict__ BH, const uint32_t* __restrict__ BL,
                        const float* __restrict__ Wfp,
                        const float* __restrict__ bias,
                        const float* __restrict__ scale, const float* __restrict__ shift,
                        float* __restrict__ Cmat,
                        float* __restrict__ gsum, float* __restrict__ gsq,
                        int Kdim, int Ndim)
{
    extern __shared__ uint32_t smw[];
    const int tid = threadIdx.x;
    const int m0 = blockIdx.y * 128, n0 = blockIdx.x * 128;

    if (blockIdx.y % 3 != 2) {
        // ================= TENSOR PATH (R8 config) =================
        const uint32_t sbase = smem_u32(smw);
        const int w = tid >> 5, lane = tid & 31;
        const int Kw = Kdim >> 1;

        const int aRow = tid >> 1;
        const int half = tid & 1;
        const int sOffA = aRow * SROW_W + half * 4;
        const float*    Ap  = Afp + (size_t)(m0 + aRow) * Kdim + half * 8;
        const uint32_t* BHp = BH + (size_t)(n0 + aRow) * Kw + half * 4;
        const uint32_t* BLp = BL + (size_t)(n0 + aRow) * Kw + half * 4;

        const int nch = Kdim >> 4;

        float acc[4][4][4];
        #pragma unroll
        for (int i = 0; i < 4; i++)
            #pragma unroll
            for (int j = 0; j < 4; j++)
                #pragma unroll
                for (int e = 0; e < 4; e++) acc[i][j][e] = 0.0f;

        float4 ra0, ra1;

        auto issueB = [&](int buf, int c) {
            CPASYNC16(sbase + 4u * (buf * BUFF_W + OFF_BH + sOffA), BHp + c * 8);
            CPASYNC16(sbase + 4u * (buf * BUFF_W + OFF_BL + sOffA), BLp + c * 8);
        };
        auto loadA = [&](int c) {
            ra0 = *(const float4*)(Ap + c * 16);
            ra1 = *(const float4*)(Ap + c * 16 + 4);
        };
        auto storeA = [&](int buf, int kc) {
            uint32_t* S = smw + buf * BUFF_W;
            float av[8] = {ra0.x, ra0.y, ra0.z, ra0.w, ra1.x, ra1.y, ra1.z, ra1.w};
            if (NORM) {
                const float* scp = scale + kc * 16 + half * 8;
                const float* shp = shift + kc * 16 + half * 8;
                #pragma unroll
                for (int j = 0; j < 8; j++)
                    av[j] = fmaxf(fmaf(scp[j], av[j], shp[j]), 0.0f);
            }
            uint32_t hw[4], lw[4];
            #pragma unroll
            for (int p = 0; p < 4; p++) split2(av[2 * p], av[2 * p + 1], hw[p], lw[p]);
            *(uint4*)(S + sOffA)          = make_uint4(hw[0], hw[1], hw[2], hw[3]);
            *(uint4*)(S + OFF_AL + sOffA) = make_uint4(lw[0], lw[1], lw[2], lw[3]);
        };

        issueB(0, 0);
        loadA(0);
        storeA(0, 0);
        CPCOMMIT();
        CPWAIT0();
        __syncthreads();

        const int mtb = (w & 1) * 64;
        const int ntb = (w >> 1) * 32;
        const int fr = lane >> 2;
        const int fc = lane & 3;

        const int rA = mtb + ((lane >> 3) & 1) * 8 + (lane & 7);
        const int wA = (lane >> 4) * 4;
        const int rB = ntb + (lane >> 4) * 8 + (lane & 7);
        const int wB = ((lane >> 3) & 1) * 4;

        for (int c = 0; c < nch; c++) {
            const int buf = c & 1;
            const uint32_t soff = sbase + 4u * (buf * BUFF_W);
            if (c + 1 < nch) {
                issueB(buf ^ 1, c + 1);
                CPCOMMIT();
                loadA(c + 1);
            }

            uint32_t aF[4][4], bF[4][2];
            // A-hi
            #pragma unroll
            for (int i = 0; i < 4; i++) {
                uint32_t ad = soff + 4u * ((uint32_t)(rA + i * 16) * SROW_W + wA);
                LDSM4(aF[i][0], aF[i][1], aF[i][2], aF[i][3], ad);
            }
            // B-hi
            #pragma unroll
            for (int j2 = 0; j2 < 2; j2++) {
                uint32_t ad = soff + 4u * (OFF_BH + (uint32_t)(rB + j2 * 16) * SROW_W + wB);
                LDSM4(bF[2 * j2][0], bF[2 * j2][1], bF[2 * j2 + 1][0], bF[2 * j2 + 1][1], ad);
            }
            #pragma unroll
            for (int i = 0; i < 4; i++)
                #pragma unroll
                for (int j = 0; j < 4; j++)
                    mma16(acc[i][j], aF[i], bF[j]);
            // B-lo (A-hi resident)
            #pragma unroll
            for (int j2 = 0; j2 < 2; j2++) {
                uint32_t ad = soff + 4u * (OFF_BL + (uint32_t)(rB + j2 * 16) * SROW_W + wB);
                LDSM4(bF[2 * j2][0], bF[2 * j2][1], bF[2 * j2 + 1][0], bF[2 * j2 + 1][1], ad);
            }
            #pragma unroll
            for (int i = 0; i < 4; i++)
                #pragma unroll
                for (int j = 0; j < 4; j++)
                    mma16(acc[i][j], aF[i], bF[j]);
            // A-lo x B-hi
            #pragma unroll
            for (int i = 0; i < 4; i++) {
                uint32_t ad = soff + 4u * (OFF_AL + (uint32_t)(rA + i * 16) * SROW_W + wA);
                LDSM4(aF[i][0], aF[i][1], aF[i][2], aF[i][3], ad);
            }
            #pragma unroll
            for (int j2 = 0; j2 < 2; j2++) {
                uint32_t ad = soff + 4u * (OFF_BH + (uint32_t)(rB + j2 * 16) * SROW_W + wB);
                LDSM4(bF[2 * j2][0], bF[2 * j2][1], bF[2 * j2 + 1][0], bF[2 * j2 + 1][1], ad);
            }
            #pragma unroll
            for (int i = 0; i < 4; i++)
                #pragma unroll
                for (int j = 0; j < 4; j++)
                    mma16(acc[i][j], aF[i], bF[j]);

            if (c + 1 < nch) {
                storeA(buf ^ 1, c + 1);
                CPWAIT0();
            }
            __syncthreads();
        }

        // Epilogue
        const int er = m0 + mtb + fr;
        const int ec = n0 + ntb + fc * 2;
        #pragma unroll
        for (int j = 0; j < 4; j++) {
            int cc = ec + j * 8;
            float2 b2 = *(const float2*)(bias + cc);
            float s0 = 0.f, s1 = 0.f, q0 = 0.f, q1 = 0.f;
            #pragma unroll
            for (int i = 0; i < 4; i++) {
                int r = er + i * 16;
                float o00 = acc[i][j][0] + b2.x, o01 = acc[i][j][1] + b2.y;
                float o10 = acc[i][j][2] + b2.x, o11 = acc[i][j][3] + b2.y;
                *(float2*)(Cmat + (size_t)r * Ndim + cc)       = make_float2(o00, o01);
                *(float2*)(Cmat + (size_t)(r + 8) * Ndim + cc) = make_float2(o10, o11);
                s0 += o00 + o10; s1 += o01 + o11;
                q0 += o00 * o00 + o10 * o10;
                q1 += o01 * o01 + o11 * o11;
            }
            #pragma unroll
            for (int off = 4; off < 32; off <<= 1) {
                s0 += __shfl_xor_sync(0xffffffffu, s0, off);
                s1 += __shfl_xor_sync(0xffffffffu, s1, off);
                q0 += __shfl_xor_sync(0xffffffffu, q0, off);
                q1 += __shfl_xor_sync(0xffffffffu, q1, off);
            }
            if (fr == 0) {
                atomicAdd(&gsum[cc], s0);
                atomicAdd(&gsum[cc + 1], s1);
                atomicAdd(&gsq[cc], q0);
                atomicAdd(&gsq[cc + 1], q1);
            }
        }
    } else {
        // ================= FFMA PATH (exact fp32, R3 config) =================
        float* smf = (float*)smw;
        float (*As)[132] = (float(*)[132])smf;
        float (*Bs)[132] = (float(*)[132])(smf + 16 * 132);

        const int ty = tid >> 4, tx = tid & 15;

        float acc[8][8];
        #pragma unroll
        for (int i = 0; i < 8; i++)
            #pragma unroll
            for (int j = 0; j < 8; j++) acc[i][j] = 0.0f;

        const float* Aptr = Afp + (size_t)m0 * Kdim;
        const float* Wptr = Wfp + (size_t)n0 * Kdim;
        const int fA = tid * 2;

        for (int k0 = 0; k0 < Kdim; k0 += 16) {
            #pragma unroll
            for (int i = 0; i < 2; i++) {
                int f = fA + i;
                int row = f >> 2;
                int kq = (f & 3) * 4;
                float4 v = *(const float4*)(Aptr + (size_t)row * Kdim + k0 + kq);
                if (NORM) {
                    int k = k0 + kq;
                    v.x = fmaxf(fmaf(scale[k + 0], v.x, shift[k + 0]), 0.0f);
                    v.y = fmaxf(fmaf(scale[k + 1], v.y, shift[k + 1]), 0.0f);
                    v.z = fmaxf(fmaf(scale[k + 2], v.z, shift[k + 2]), 0.0f);
                    v.w = fmaxf(fmaf(scale[k + 3], v.w, shift[k + 3]), 0.0f);
                }
                As[kq + 0][row] = v.x; As[kq + 1][row] = v.y;
                As[kq + 2][row] = v.z; As[kq + 3][row] = v.w;
                float4 u = *(const float4*)(Wptr + (size_t)row * Kdim + k0 + kq);
                Bs[kq + 0][row] = u.x; Bs[kq + 1][row] = u.y;
                Bs[kq + 2][row] = u.z; Bs[kq + 3][row] = u.w;
            }
            __syncthreads();
            #pragma unroll
            for (int kk = 0; kk < 16; kk++) {
                float a[8], bb[8];
                *(float4*)(a)      = *(const float4*)&As[kk][ty * 8];
                *(float4*)(a + 4)  = *(const float4*)&As[kk][ty * 8 + 4];
                *(float4*)(bb)     = *(const float4*)&Bs[kk][tx * 8];
                *(float4*)(bb + 4) = *(const float4*)&Bs[kk][tx * 8 + 4];
                #pragma unroll
                for (int i = 0; i < 8; i++)
                    #pragma unroll
                    for (int j = 0; j < 8; j++)
                        acc[i][j] = fmaf(a[i], bb[j], acc[i][j]);
            }
            __syncthreads();
        }

        float bv[8];
        #pragma unroll
        for (int j = 0; j < 8; j++) bv[j] = bias[n0 + tx * 8 + j];

        float cs[8], cq[8];
        #pragma unroll
        for (int j = 0; j < 8; j++) { cs[j] = 0.0f; cq[j] = 0.0f; }

        #pragma unroll
        for (int i = 0; i < 8; i++) {
            int r = m0 + ty * 8 + i;
            float o[8];
            #pragma unroll
            for (int j = 0; j < 8; j++) {
                o[j] = acc[i][j] + bv[j];
                cs[j] += o[j];
                cq[j] += o[j] * o[j];
            }
            float* crow = Cmat + (size_t)r * Ndim + n0 + tx * 8;
            *(float4*)(crow)     = make_float4(o[0], o[1], o[2], o[3]);
            *(float4*)(crow + 4) = make_float4(o[4], o[5], o[6], o[7]);
        }

        // stats: smem column reduction, then 1 global atomic per column
        __syncthreads();
        smf[tid] = 0.0f;     // colsum [0..127], colsq [128..255]
        __syncthreads();
        #pragma unroll
        for (int j = 0; j < 8; j++) {
            atomicAdd(&smf[tx * 8 + j], cs[j]);
            atomicAdd(&smf[128 + tx * 8 + j], cq[j]);
        }
        __syncthreads();
        if (tid < 128) {
            atomicAdd(&gsum[n0 + tid], smf[tid]);
            atomicAdd(&gsq[n0 + tid], smf[128 + tid]);
        }
    }
}

// ---------------- finalize BN affine (self-zeroing accumulators) ----------------
__global__ void finalize_kernel(float* __restrict__ sum, float* __restrict__ sq,
                                const float* __restrict__ g, const float* __restrict__ be,
                                float* __restrict__ scale, float* __restrict__ shift, int Cdim)
{
    int c = blockIdx.x * blockDim.x + threadIdx.x;
    if (c < Cdim) {
        const float invM = 1.0f / (float)MTOT;
        float mean = sum[c] * invM;
        float var  = sq[c] * invM - mean * mean;
        float inv  = rsqrtf(var + BN_EPS);
        float sc   = g[c] * inv;
        scale[c] = sc;
        shift[c] = be[c] - mean * sc;
        sum[c] = 0.0f;   // reset for next replay
        sq[c]  = 0.0f;
    }
}

// ---------------- final: normalize+relu layer3 and transpose to [B, C3, NY] ----------------
__global__ __launch_bounds__(256)
void trans_norm_kernel(const float* __restrict__ z3, const float* __restrict__ sc,
                       const float* __restrict__ sh, float* __restrict__ out)
{
    __shared__ float tile[32][33];
    int m0 = blockIdx.x * 32;
    int c0 = blockIdx.y * 32;
    int tx = threadIdx.x, ty = threadIdx.y;
    #pragma unroll
    for (int r = ty; r < 32; r += 8) {
        int c = c0 + tx;
        float v = z3[(size_t)(m0 + r) * C3 + c];
        v = fmaxf(fmaf(sc[c], v, sh[c]), 0.0f);
        tile[r][tx] = v;
    }
    __syncthreads();
    int b = m0 / NY;
    int n0 = m0 - b * NY;
    #pragma unroll
    for (int r = ty; r < 32; r += 8) {
        out[((size_t)b * C3 + c0 + r) * NY + n0 + tx] = tile[tx][r];
    }
}

// ---------------- launch ----------------
extern "C" void kernel_launch(void* const* d_in, const int* in_sizes, int n_in,
                              void* d_out, int out_size)
{
    const float* y_points = (const float*)d_in[0];
    const float* y_feats  = (const float*)d_in[1];
    const float* x_points = (const float*)d_in[2];
    const float* x_feats  = (const float*)d_in[3];
    const float* W1 = (const float*)d_in[4];
    const float* b1 = (const float*)d_in[5];
    const float* g1 = (const float*)d_in[6];
    const float* be1 = (const float*)d_in[7];
    const float* W2 = (const float*)d_in[8];
    const float* b2 = (const float*)d_in[9];
    const float* g2 = (const float*)d_in[10];
    const float* be2 = (const float*)d_in[11];
    const float* W3 = (const float*)d_in[12];
    const float* b3 = (const float*)d_in[13];
    const float* g3 = (const float*)d_in[14];
    const float* be3 = (const float*)d_in[15];
    float* out = (float*)d_out;

    float *feat, *z1, *z2, *z3, *red, *aff;
    uint32_t *w1h, *w1l, *w2h, *w2l, *w3h, *w3l;
    cudaGetSymbolAddress((void**)&feat, g_feat);
    cudaGetSymbolAddress((void**)&z1, g_z1);
    cudaGetSymbolAddress((void**)&z2, g_z2);
    cudaGetSymbolAddress((void**)&z3, g_z3);
    cudaGetSymbolAddress((void**)&red, g_red);
    cudaGetSymbolAddress((void**)&aff, g_aff);
    cudaGetSymbolAddress((void**)&w1h, g_w1h);
    cudaGetSymbolAddress((void**)&w1l, g_w1l);
    cudaGetSymbolAddress((void**)&w2h, g_w2h);
    cudaGetSymbolAddress((void**)&w2l, g_w2l);
    cudaGetSymbolAddress((void**)&w3h, g_w3h);
    cudaGetSymbolAddress((void**)&w3l, g_w3l);

    float* sum1 = red + 0;    float* sq1 = red + 512;
    float* sum2 = red + 1024; float* sq2 = red + 1280;
    float* sum3 = red + 1536; float* sq3 = red + 1664;
    float* sc1 = aff + 0;     float* sh1 = aff + 512;
    float* sc2 = aff + 1024;  float* sh2 = aff + 1280;
    float* sc3 = aff + 1536;  float* sh3 = aff + 1664;

    cudaFuncSetAttribute(hybrid_gemm_kernel<false>, cudaFuncAttributeMaxDynamicSharedMemorySize, GEMM_SMEM);
    cudaFuncSetAttribute(hybrid_gemm_kernel<true>,  cudaFuncAttributeMaxDynamicSharedMemorySize, GEMM_SMEM);

    split_w_all_kernel<<<(W1W + W2W + W3W + 255) / 256, 256>>>(
        W1, W2, W3, w1h, w1l, w2h, w2l, w3h, w3l);

    knn_interp_kernel<<<dim3(NY / 256, BATCH), 256>>>(y_points, y_feats, x_points, x_feats, feat);

    hybrid_gemm_kernel<false><<<dim3(C1 / 128, MTOT / 128), 256, GEMM_SMEM>>>(
        feat, w1h, w1l, W1, b1, nullptr, nullptr, z1, sum1, sq1, DIMF, C1);
    finalize_kernel<<<2, 256>>>(sum1, sq1, g1, be1, sc1, sh1, C1);

    hybrid_gemm_kernel<true><<<dim3(C2 / 128, MTOT / 128), 256, GEMM_SMEM>>>(
        z1, w2h, w2l, W2, b2, sc1, sh1, z2, sum2, sq2, C1, C2);
    finalize_kernel<<<1, 256>>>(sum2, sq2, g2, be2, sc2, sh2, C2);

    hybrid_gemm_kernel<true><<<dim3(C3 / 128, MTOT / 128), 256, GEMM_SMEM>>>(
        z2, w3h, w3l, W3, b3, sc2, sh2, z3, sum3, sq3, C2, C3);
    finalize_kernel<<<1, 128>>>(sum3, sq3, g3, be3, sc3, sh3, C3);

    trans_norm_kernel<<<dim3(MTOT / 32, C3 / 32), dim3(32, 8)>>>(z3, sc3, sh3, out);
}

// round 13
// speedup vs baseline: 1.3009x; 1.3009x over previous
#include <cuda_runtime.h>
#include <cuda_bf16.h>
#include <cstdint>

// Problem constants
#define BATCH 4
#define NY 16384
#define NX 4096
#define CY 128
#define CX 256
#define DIMF 384       // CY + CX
#define C1 512
#define C2 256
#define C3 128
#define MTOT (BATCH*NY)   // 65536
#define IEPS 1e-8f
#define BN_EPS 1e-5f

// ---------------- scratch (device globals; no runtime alloc) ----------------
__device__ float g_feat[(size_t)MTOT * DIMF];
__device__ float g_z1[(size_t)MTOT * C1];
__device__ float g_z2[(size_t)MTOT * C2];
__device__ float g_z3[(size_t)MTOT * C3];
__device__ float g_red[1792];   // zero-initialized at load; finalize self-zeroes
__device__ float g_aff[1792];
// pre-split weights (bf16x2 words, row-major [N][K/2])
#define W1W (C1 * DIMF / 2)
#define W2W (C2 * C1 / 2)
#define W3W (C3 * C2 / 2)
__device__ uint32_t g_w1h[W1W], g_w1l[W1W];
__device__ uint32_t g_w2h[W2W], g_w2l[W2W];
__device__ uint32_t g_w3h[W3W], g_w3l[W3W];

// pack two floats to bf16x2 (a -> low half, b -> high half)
__device__ __forceinline__ uint32_t cvt2bf(float lo, float hi) {
    uint32_t r;
    asm("cvt.rn.bf16x2.f32 %0, %1, %2;" : "=r"(r) : "f"(hi), "f"(lo));
    return r;
}
__device__ __forceinline__ void split2(float a, float b, uint32_t& h, uint32_t& l) {
    h = cvt2bf(a, b);
    float h0 = __uint_as_float(h << 16);
    float h1 = __uint_as_float(h & 0xffff0000u);
    l = cvt2bf(a - h0, b - h1);
}

// m16n8k16 BF16 mma
__device__ __forceinline__ void mma16(float* c, const uint32_t* a, const uint32_t* b) {
    asm volatile(
        "mma.sync.aligned.m16n8k16.row.col.f32.bf16.bf16.f32 "
        "{%0,%1,%2,%3}, {%4,%5,%6,%7}, {%8,%9}, {%0,%1,%2,%3};"
        : "+f"(c[0]), "+f"(c[1]), "+f"(c[2]), "+f"(c[3])
        : "r"(a[0]), "r"(a[1]), "r"(a[2]), "r"(a[3]),
          "r"(b[0]), "r"(b[1]));
}
#define LDSM4(r0, r1, r2, r3, addr) \
    asm volatile("ldmatrix.sync.aligned.m8n8.x4.shared.b16 {%0,%1,%2,%3}, [%4];" \
        : "=r"(r0), "=r"(r1), "=r"(r2), "=r"(r3) : "r"(addr))
#define CPASYNC16(dst, src) \
    asm volatile("cp.async.cg.shared.global [%0], [%1], 16;" :: "r"(dst), "l"(src))
#define CPCOMMIT()  asm volatile("cp.async.commit_group;" ::: "memory")
#define CPWAIT0()   asm volatile("cp.async.wait_group 0;" ::: "memory")

__device__ __forceinline__ uint32_t smem_u32(const void* p) {
    uint32_t a;
    asm("{ .reg .u64 t; cvta.to.shared.u64 t, %1; cvt.u32.u64 %0, t; }" : "=r"(a) : "l"(p));
    return a;
}

// ---------------- combined weight split prep (one launch) ----------------
__global__ void split_w_all_kernel(const float* __restrict__ W1f, const float* __restrict__ W2f,
                                   const float* __restrict__ W3f,
                                   uint32_t* __restrict__ w1h, uint32_t* __restrict__ w1l,
                                   uint32_t* __restrict__ w2h, uint32_t* __restrict__ w2l,
                                   uint32_t* __restrict__ w3h, uint32_t* __restrict__ w3l)
{
    int i = blockIdx.x * blockDim.x + threadIdx.x;
    const float* W; uint32_t *H, *L; int idx;
    if (i < W1W) { W = W1f; H = w1h; L = w1l; idx = i; }
    else if (i < W1W + W2W) { W = W2f; H = w2h; L = w2l; idx = i - W1W; }
    else if (i < W1W + W2W + W3W) { W = W3f; H = w3h; L = w3l; idx = i - W1W - W2W; }
    else return;
    uint32_t h, l;
    split2(W[2 * idx], W[2 * idx + 1], h, l);
    H[idx] = h; L[idx] = l;
}

// ---------------- KNN + interpolation + concat, 2 y-points per thread ----------------
// Exact fp32 op-tree per distance:
//   psq = (y0*y0 + y1*y1) + y2*y2
//   dot = fma(y2,x2, fma(y1,x1, mul(y0,x0)))
//   d   = (psq + xsq) - (2*dot)
// grid: (NY/512, BATCH), block 256; thread handles points n and n+256.
#define NXC 2048
__global__ __launch_bounds__(256)
void knn_interp_kernel(const float* __restrict__ yp, const float* __restrict__ yf,
                       const float* __restrict__ xp, const float* __restrict__ xf,
                       float* __restrict__ feat)
{
    __shared__ float4 s_pt[NXC];
    int b = blockIdx.y;
    int tid = threadIdx.x;
    int n = blockIdx.x * 512 + tid;
    int mA = b * NY + n;
    int mB = mA + 256;

    const float* xpb = xp + (size_t)b * NX * 3;

    float pxA = yp[(size_t)mA * 3 + 0];
    float pyA = yp[(size_t)mA * 3 + 1];
    float pzA = yp[(size_t)mA * 3 + 2];
    float psqA = __fadd_rn(__fadd_rn(__fmul_rn(pxA, pxA), __fmul_rn(pyA, pyA)),
                           __fmul_rn(pzA, pzA));
    float pxB = yp[(size_t)mB * 3 + 0];
    float pyB = yp[(size_t)mB * 3 + 1];
    float pzB = yp[(size_t)mB * 3 + 2];
    float psqB = __fadd_rn(__fadd_rn(__fmul_rn(pxB, pxB), __fmul_rn(pyB, pyB)),
                           __fmul_rn(pzB, pzB));

    float dA0 = 3.4e38f, dA1 = 3.4e38f, dA2 = 3.4e38f;
    int   iA0 = 0, iA1 = 0, iA2 = 0;
    float dB0 = 3.4e38f, dB1 = 3.4e38f, dB2 = 3.4e38f;
    int   iB0 = 0, iB1 = 0, iB2 = 0;

    for (int ch = 0; ch < NX; ch += NXC) {
        __syncthreads();
        for (int j = tid; j < NXC; j += 256) {
            const float* xq = xpb + 3 * (size_t)(ch + j);
            float x = xq[0], y = xq[1], z = xq[2];
            float xsq = __fadd_rn(__fadd_rn(__fmul_rn(x, x), __fmul_rn(y, y)),
                                  __fmul_rn(z, z));
            s_pt[j] = make_float4(x, y, z, xsq);
        }
        __syncthreads();
        #pragma unroll 4
        for (int j = 0; j < NXC; j++) {
            float4 q = s_pt[j];
            // two independent dependency chains -> 2x ILP
            float dotA = __fmaf_rn(pzA, q.z, __fmaf_rn(pyA, q.y, __fmul_rn(pxA, q.x)));
            float dotB = __fmaf_rn(pzB, q.z, __fmaf_rn(pyB, q.y, __fmul_rn(pxB, q.x)));
            float dA = __fsub_rn(__fadd_rn(psqA, q.w), __fmul_rn(2.0f, dotA));
            float dB = __fsub_rn(__fadd_rn(psqB, q.w), __fmul_rn(2.0f, dotB));
            if (dA < dA2) {
                int jj = ch + j;
                if (dA < dA1) {
                    dA2 = dA1; iA2 = iA1;
                    if (dA < dA0) { dA1 = dA0; iA1 = iA0; dA0 = dA; iA0 = jj; }
                    else          { dA1 = dA; iA1 = jj; }
                } else { dA2 = dA; iA2 = jj; }
            }
            if (dB < dB2) {
                int jj = ch + j;
                if (dB < dB1) {
                    dB2 = dB1; iB2 = iB1;
                    if (dB < dB0) { dB1 = dB0; iB1 = iB0; dB0 = dB; iB0 = jj; }
                    else          { dB1 = dB; iB1 = jj; }
                } else { dB2 = dB; iB2 = jj; }
            }
        }
    }

    // weights for both point sets
    float wA0 = 1.0f / (dA0 + IEPS), wA1 = 1.0f / (dA1 + IEPS), wA2 = 1.0f / (dA2 + IEPS);
    float wsA = 1.0f / (wA0 + wA1 + wA2);
    wA0 *= wsA; wA1 *= wsA; wA2 *= wsA;
    float wB0 = 1.0f / (dB0 + IEPS), wB1 = 1.0f / (dB1 + IEPS), wB2 = 1.0f / (dB2 + IEPS);
    float wsB = 1.0f / (wB0 + wB1 + wB2);
    wB0 *= wsB; wB1 *= wsB; wB2 *= wsB;

    int lane = tid & 31;
    const float* xfb = xf + (size_t)b * NX * CX;
    unsigned mask = 0xffffffffu;

    #pragma unroll
    for (int set = 0; set < 2; set++) {
        int   ii0 = set ? iB0 : iA0, ii1 = set ? iB1 : iA1, ii2 = set ? iB2 : iA2;
        float ww0 = set ? wB0 : wA0, ww1 = set ? wB1 : wA1, ww2 = set ? wB2 : wA2;
        int   mbase = (set ? mB : mA) - lane;
        for (int s = 0; s < 32; s++) {
            int   j0 = __shfl_sync(mask, ii0, s);
            int   j1 = __shfl_sync(mask, ii1, s);
            int   j2 = __shfl_sync(mask, ii2, s);
            float a0 = __shfl_sync(mask, ww0, s);
            float a1 = __shfl_sync(mask, ww1, s);
            float a2 = __shfl_sync(mask, ww2, s);
            int ms = mbase + s;
            float* frow = feat + (size_t)ms * DIMF;
            const float4* ysrc = (const float4*)(yf + (size_t)ms * CY);
            ((float4*)frow)[lane] = ysrc[lane];
            const float4* r0 = (const float4*)(xfb + (size_t)j0 * CX);
            const float4* r1 = (const float4*)(xfb + (size_t)j1 * CX);
            const float4* r2 = (const float4*)(xfb + (size_t)j2 * CX);
            float4* dst = (float4*)(frow + CY);
            #pragma unroll
            for (int h = 0; h < 2; h++) {
                int c4 = h * 32 + lane;
                float4 v0 = r0[c4], v1 = r1[c4], v2 = r2[c4];
                float4 o;
                o.x = a0 * v0.x + a1 * v1.x + a2 * v2.x;
                o.y = a0 * v0.y + a1 * v1.y + a2 * v2.y;
                o.z = a0 * v0.z + a1 * v1.z + a2 * v2.z;
                o.w = a0 * v0.w + a1 * v1.w + a2 * v2.w;
                dst[c4] = o;
            }
        }
    }
}

// ---------------- mma.sync 3xBF16 GEMM + fused BN stats (R8 config) ----------------
// Block tile 128x128x16, 8 warps (2m x 4n), warp tile 64x32.
// A: fp32 (+optional affine/relu), split at STS. B: pre-split, cp.async copy.
#define SROW_W 12
#define A_W   (128 * SROW_W)             // 1536 words per operand array
#define OFF_AL A_W
#define OFF_BH (2 * A_W)
#define OFF_BL (3 * A_W)
#define BUFF_W (4 * A_W)                 // 6144 words per buffer
#define GEMM_SMEM (2 * BUFF_W * 4)       // 49152 bytes

template<bool NORM>
__global__ __launch_bounds__(256)
void mma_gemm_kernel(const float* __restrict__ Afp,
                     const uint32_t* __restrict__ BH, const uint32_t* __restrict__ BL,
                     const float* __restrict__ bias,
                     const float* __restrict__ scale, const float* __restrict__ shift,
                     float* __restrict__ Cmat,
                     float* __restrict__ gsum, float* __restrict__ gsq,
                     int Kdim, int Ndim)
{
    extern __shared__ uint32_t smw[];
    const uint32_t sbase = smem_u32(smw);
    const int tid = threadIdx.x;
    const int w = tid >> 5, lane = tid & 31;
    const int m0 = blockIdx.y * 128, n0 = blockIdx.x * 128;
    const int Kw = Kdim >> 1;

    const int aRow = tid >> 1;
    const int half = tid & 1;
    const int sOffA = aRow * SROW_W + half * 4;
    const float*    Ap  = Afp + (size_t)(m0 + aRow) * Kdim + half * 8;
    const uint32_t* BHp = BH + (size_t)(n0 + aRow) * Kw + half * 4;
    const uint32_t* BLp = BL + (size_t)(n0 + aRow) * Kw + half * 4;

    const int nch = Kdim >> 4;

    float acc[4][4][4];
    #pragma unroll
    for (int i = 0; i < 4; i++)
        #pragma unroll
        for (int j = 0; j < 4; j++)
            #pragma unroll
            for (int e = 0; e < 4; e++) acc[i][j][e] = 0.0f;

    float4 ra0, ra1;

    auto issueB = [&](int buf, int c) {
        CPASYNC16(sbase + 4u * (buf * BUFF_W + OFF_BH + sOffA), BHp + c * 8);
        CPASYNC16(sbase + 4u * (buf * BUFF_W + OFF_BL + sOffA), BLp + c * 8);
    };
    auto loadA = [&](int c) {
        ra0 = *(const float4*)(Ap + c * 16);
        ra1 = *(const float4*)(Ap + c * 16 + 4);
    };
    auto storeA = [&](int buf, int kc) {
        uint32_t* S = smw + buf * BUFF_W;
        float av[8] = {ra0.x, ra0.y, ra0.z, ra0.w, ra1.x, ra1.y, ra1.z, ra1.w};
        if (NORM) {
            const float* scp = scale + kc * 16 + half * 8;
            const float* shp = shift + kc * 16 + half * 8;
            #pragma unroll
            for (int j = 0; j < 8; j++)
                av[j] = fmaxf(fmaf(scp[j], av[j], shp[j]), 0.0f);
        }
        uint32_t hw[4], lw[4];
        #pragma unroll
        for (int p = 0; p < 4; p++) split2(av[2 * p], av[2 * p + 1], hw[p], lw[p]);
        *(uint4*)(S + sOffA)          = make_uint4(hw[0], hw[1], hw[2], hw[3]);
        *(uint4*)(S + OFF_AL + sOffA) = make_uint4(lw[0], lw[1], lw[2], lw[3]);
    };

    issueB(0, 0);
    loadA(0);
    storeA(0, 0);
    CPCOMMIT();
    CPWAIT0();
    __syncthreads();

    const int mtb = (w & 1) * 64;
    const int ntb = (w >> 1) * 32;
    const int fr = lane >> 2;
    const int fc = lane & 3;

    const int rA = mtb + ((lane >> 3) & 1) * 8 + (lane & 7);
    const int wA = (lane >> 4) * 4;
    const int rB = ntb + (lane >> 4) * 8 + (lane & 7);
    const int wB = ((lane >> 3) & 1) * 4;

    for (int c = 0; c < nch; c++) {
        const int buf = c & 1;
        const uint32_t soff = sbase + 4u * (buf * BUFF_W);
        if (c + 1 < nch) {
            issueB(buf ^ 1, c + 1);
            CPCOMMIT();
            loadA(c + 1);
        }

        uint32_t aF[4][4], bF[4][2];
        // A-hi
        #pragma unroll
        for (int i = 0; i < 4; i++) {
            uint32_t ad = soff + 4u * ((uint32_t)(rA + i * 16) * SROW_W + wA);
            LDSM4(aF[i][0], aF[i][1], aF[i][2], aF[i][3], ad);
        }
        // B-hi
        #pragma unroll
        for (int j2 = 0; j2 < 2; j2++) {
            uint32_t ad = soff + 4u * (OFF_BH + (uint32_t)(rB + j2 * 16) * SROW_W + wB);
            LDSM4(bF[2 * j2][0], bF[2 * j2][1], bF[2 * j2 + 1][0], bF[2 * j2 + 1][1], ad);
        }
        #pragma unroll
        for (int i = 0; i < 4; i++)
            #pragma unroll
            for (int j = 0; j < 4; j++)
                mma16(acc[i][j], aF[i], bF[j]);
        // B-lo (A-hi resident)
        #pragma unroll
        for (int j2 = 0; j2 < 2; j2++) {
            uint32_t ad = soff + 4u * (OFF_BL + (uint32_t)(rB + j2 * 16) * SROW_W + wB);
            LDSM4(bF[2 * j2][0], bF[2 * j2][1], bF[2 * j2 + 1][0], bF[2 * j2 + 1][1], ad);
        }
        #pragma unroll
        for (int i = 0; i < 4; i++)
            #pragma unroll
            for (int j = 0; j < 4; j++)
                mma16(acc[i][j], aF[i], bF[j]);
        // A-lo x B-hi
        #pragma unroll
        for (int i = 0; i < 4; i++) {
            uint32_t ad = soff + 4u * (OFF_AL + (uint32_t)(rA + i * 16) * SROW_W + wA);
            LDSM4(aF[i][0], aF[i][1], aF[i][2], aF[i][3], ad);
        }
        #pragma unroll
        for (int j2 = 0; j2 < 2; j2++) {
            uint32_t ad = soff + 4u * (OFF_BH + (uint32_t)(rB + j2 * 16) * SROW_W + wB);
            LDSM4(bF[2 * j2][0], bF[2 * j2][1], bF[2 * j2 + 1][0], bF[2 * j2 + 1][1], ad);
        }
        #pragma unroll
        for (int i = 0; i < 4; i++)
            #pragma unroll
            for (int j = 0; j < 4; j++)
                mma16(acc[i][j], aF[i], bF[j]);

        if (c + 1 < nch) {
            storeA(buf ^ 1, c + 1);
            CPWAIT0();
        }
        __syncthreads();
    }

    // Epilogue: write C (+bias) and accumulate per-column sum/sumsq.
    const int er = m0 + mtb + fr;
    const int ec = n0 + ntb + fc * 2;
    #pragma unroll
    for (int j = 0; j < 4; j++) {
        int cc = ec + j * 8;
        float2 b2 = *(const float2*)(bias + cc);
        float s0 = 0.f, s1 = 0.f, q0 = 0.f, q1 = 0.f;
        #pragma unroll
        for (int i = 0; i < 4; i++) {
            int r = er + i * 16;
            float o00 = acc[i][j][0] + b2.x, o01 = acc[i][j][1] + b2.y;
            float o10 = acc[i][j][2] + b2.x, o11 = acc[i][j][3] + b2.y;
            *(float2*)(Cmat + (size_t)r * Ndim + cc)       = make_float2(o00, o01);
            *(float2*)(Cmat + (size_t)(r + 8) * Ndim + cc) = make_float2(o10, o11);
            s0 += o00 + o10; s1 += o01 + o11;
            q0 += o00 * o00 + o10 * o10;
            q1 += o01 * o01 + o11 * o11;
        }
        #pragma unroll
        for (int off = 4; off < 32; off <<= 1) {
            s0 += __shfl_xor_sync(0xffffffffu, s0, off);
            s1 += __shfl_xor_sync(0xffffffffu, s1, off);
            q0 += __shfl_xor_sync(0xffffffffu, q0, off);
            q1 += __shfl_xor_sync(0xffffffffu, q1, off);
        }
        if (fr == 0) {
            atomicAdd(&gsum[cc], s0);
            atomicAdd(&gsum[cc + 1], s1);
            atomicAdd(&gsq[cc], q0);
            atomicAdd(&gsq[cc + 1], q1);
        }
    }
}

// ---------------- finalize BN affine (self-zeroing accumulators) ----------------
__global__ void finalize_kernel(float* __restrict__ sum, float* __restrict__ sq,
                                const float* __restrict__ g, const float* __restrict__ be,
                                float* __restrict__ scale, float* __restrict__ shift, int Cdim)
{
    int c = blockIdx.x * blockDim.x + threadIdx.x;
    if (c < Cdim) {
        const float invM = 1.0f / (float)MTOT;
        float mean = sum[c] * invM;
        float var  = sq[c] * invM - mean * mean;
        float inv  = rsqrtf(var + BN_EPS);
        float sc   = g[c] * inv;
        scale[c] = sc;
        shift[c] = be[c] - mean * sc;
        sum[c] = 0.0f;   // reset for next replay
        sq[c]  = 0.0f;
    }
}

// ---------------- final: normalize+relu layer3 and transpose to [B, C3, NY] ----------------
__global__ __launch_bounds__(256)
void trans_norm_kernel(const float* __restrict__ z3, const float* __restrict__ sc,
                       const float* __restrict__ sh, float* __restrict__ out)
{
    __shared__ float tile[32][33];
    int m0 = blockIdx.x * 32;
    int c0 = blockIdx.y * 32;
    int tx = threadIdx.x, ty = threadIdx.y;
    #pragma unroll
    for (int r = ty; r < 32; r += 8) {
        int c = c0 + tx;
        float v = z3[(size_t)(m0 + r) * C3 + c];
        v = fmaxf(fmaf(sc[c], v, sh[c]), 0.0f);
        tile[r][tx] = v;
    }
    __syncthreads();
    int b = m0 / NY;
    int n0 = m0 - b * NY;
    #pragma unroll
    for (int r = ty; r < 32; r += 8) {
        out[((size_t)b * C3 + c0 + r) * NY + n0 + tx] = tile[tx][r];
    }
}

// ---------------- launch ----------------
extern "C" void kernel_launch(void* const* d_in, const int* in_sizes, int n_in,
                              void* d_out, int out_size)
{
    const float* y_points = (const float*)d_in[0];
    const float* y_feats  = (const float*)d_in[1];
    const float* x_points = (const float*)d_in[2];
    const float* x_feats  = (const float*)d_in[3];
    const float* W1 = (const float*)d_in[4];
    const float* b1 = (const float*)d_in[5];
    const float* g1 = (const float*)d_in[6];
    const float* be1 = (const float*)d_in[7];
    const float* W2 = (const float*)d_in[8];
    const float* b2 = (const float*)d_in[9];
    const float* g2 = (const float*)d_in[10];
    const float* be2 = (const float*)d_in[11];
    const float* W3 = (const float*)d_in[12];
    const float* b3 = (const float*)d_in[13];
    const float* g3 = (const float*)d_in[14];
    const float* be3 = (const float*)d_in[15];
    float* out = (float*)d_out;

    float *feat, *z1, *z2, *z3, *red, *aff;
    uint32_t *w1h, *w1l, *w2h, *w2l, *w3h, *w3l;
    cudaGetSymbolAddress((void**)&feat, g_feat);
    cudaGetSymbolAddress((void**)&z1, g_z1);
    cudaGetSymbolAddress((void**)&z2, g_z2);
    cudaGetSymbolAddress((void**)&z3, g_z3);
    cudaGetSymbolAddress((void**)&red, g_red);
    cudaGetSymbolAddress((void**)&aff, g_aff);
    cudaGetSymbolAddress((void**)&w1h, g_w1h);
    cudaGetSymbolAddress((void**)&w1l, g_w1l);
    cudaGetSymbolAddress((void**)&w2h, g_w2h);
    cudaGetSymbolAddress((void**)&w2l, g_w2l);
    cudaGetSymbolAddress((void**)&w3h, g_w3h);
    cudaGetSymbolAddress((void**)&w3l, g_w3l);

    float* sum1 = red + 0;    float* sq1 = red + 512;
    float* sum2 = red + 1024; float* sq2 = red + 1280;
    float* sum3 = red + 1536; float* sq3 = red + 1664;
    float* sc1 = aff + 0;     float* sh1 = aff + 512;
    float* sc2 = aff + 1024;  float* sh2 = aff + 1280;
    float* sc3 = aff + 1536;  float* sh3 = aff + 1664;

    cudaFuncSetAttribute(mma_gemm_kernel<false>, cudaFuncAttributeMaxDynamicSharedMemorySize, GEMM_SMEM);
    cudaFuncSetAttribute(mma_gemm_kernel<true>,  cudaFuncAttributeMaxDynamicSharedMemorySize, GEMM_SMEM);

    split_w_all_kernel<<<(W1W + W2W + W3W + 255) / 256, 256>>>(
        W1, W2, W3, w1h, w1l, w2h, w2l, w3h, w3l);

    knn_interp_kernel<<<dim3(NY / 512, BATCH), 256>>>(y_points, y_feats, x_points, x_feats, feat);

    mma_gemm_kernel<false><<<dim3(C1 / 128, MTOT / 128), 256, GEMM_SMEM>>>(
        feat, w1h, w1l, b1, nullptr, nullptr, z1, sum1, sq1, DIMF, C1);
    finalize_kernel<<<2, 256>>>(sum1, sq1, g1, be1, sc1, sh1, C1);

    mma_gemm_kernel<true><<<dim3(C2 / 128, MTOT / 128), 256, GEMM_SMEM>>>(
        z1, w2h, w2l, b2, sc1, sh1, z2, sum2, sq2, C1, C2);
    finalize_kernel<<<1, 256>>>(sum2, sq2, g2, be2, sc2, sh2, C2);

    mma_gemm_kernel<true><<<dim3(C3 / 128, MTOT / 128), 256, GEMM_SMEM>>>(
        z2, w3h, w3l, b3, sc2, sh2, z3, sum3, sq3, C2, C3);
    finalize_kernel<<<1, 128>>>(sum3, sq3, g3, be3, sc3, sh3, C3);

    trans_norm_kernel<<<dim3(MTOT / 32, C3 / 32), dim3(32, 8)>>>(z3, sc3, sh3, out);
}

// round 14
// speedup vs baseline: 1.4645x; 1.1257x over previous
#include <cuda_runtime.h>
#include <cuda_bf16.h>
#include <cstdint>

// Problem constants
#define BATCH 4
#define NY 16384
#define NX 4096
#define CY 128
#define CX 256
#define DIMF 384       // CY + CX
#define C1 512
#define C2 256
#define C3 128
#define MTOT (BATCH*NY)   // 65536
#define IEPS 1e-8f
#define BN_EPS 1e-5f

// ---------------- scratch (device globals; no runtime alloc) ----------------
__device__ float g_feat[(size_t)MTOT * DIMF];
__device__ float g_z1[(size_t)MTOT * C1];
__device__ float g_z2[(size_t)MTOT * C2];
__device__ float g_z3[(size_t)MTOT * C3];
__device__ float g_red[1792];   // zero at load; finalize self-zeroes for replays
__device__ float g_aff[1792];
// pre-split weights (bf16x2 words, row-major [N][K/2])
#define W1W (C1 * DIMF / 2)
#define W2W (C2 * C1 / 2)
#define W3W (C3 * C2 / 2)
__device__ uint32_t g_w1h[W1W], g_w1l[W1W];
__device__ uint32_t g_w2h[W2W], g_w2l[W2W];
__device__ uint32_t g_w3h[W3W], g_w3l[W3W];

// pack two floats to bf16x2 (a -> low half, b -> high half)
__device__ __forceinline__ uint32_t cvt2bf(float lo, float hi) {
    uint32_t r;
    asm("cvt.rn.bf16x2.f32 %0, %1, %2;" : "=r"(r) : "f"(hi), "f"(lo));
    return r;
}
__device__ __forceinline__ void split2(float a, float b, uint32_t& h, uint32_t& l) {
    h = cvt2bf(a, b);
    float h0 = __uint_as_float(h << 16);
    float h1 = __uint_as_float(h & 0xffff0000u);
    l = cvt2bf(a - h0, b - h1);
}

// m16n8k16 BF16 mma
__device__ __forceinline__ void mma16(float* c, const uint32_t* a, const uint32_t* b) {
    asm volatile(
        "mma.sync.aligned.m16n8k16.row.col.f32.bf16.bf16.f32 "
        "{%0,%1,%2,%3}, {%4,%5,%6,%7}, {%8,%9}, {%0,%1,%2,%3};"
        : "+f"(c[0]), "+f"(c[1]), "+f"(c[2]), "+f"(c[3])
        : "r"(a[0]), "r"(a[1]), "r"(a[2]), "r"(a[3]),
          "r"(b[0]), "r"(b[1]));
}
#define LDSM4(r0, r1, r2, r3, addr) \
    asm volatile("ldmatrix.sync.aligned.m8n8.x4.shared.b16 {%0,%1,%2,%3}, [%4];" \
        : "=r"(r0), "=r"(r1), "=r"(r2), "=r"(r3) : "r"(addr))
#define CPASYNC16(dst, src) \
    asm volatile("cp.async.cg.shared.global [%0], [%1], 16;" :: "r"(dst), "l"(src))
#define CPCOMMIT()  asm volatile("cp.async.commit_group;" ::: "memory")
#define CPWAIT0()   asm volatile("cp.async.wait_group 0;" ::: "memory")

__device__ __forceinline__ uint32_t smem_u32(const void* p) {
    uint32_t a;
    asm("{ .reg .u64 t; cvta.to.shared.u64 t, %1; cvt.u32.u64 %0, t; }" : "=r"(a) : "l"(p));
    return a;
}

// ---------------- combined weight split prep (one launch) ----------------
__global__ void split_w_all_kernel(const float* __restrict__ W1f, const float* __restrict__ W2f,
                                   const float* __restrict__ W3f,
                                   uint32_t* __restrict__ w1h, uint32_t* __restrict__ w1l,
                                   uint32_t* __restrict__ w2h, uint32_t* __restrict__ w2l,
                                   uint32_t* __restrict__ w3h, uint32_t* __restrict__ w3l)
{
    int i = blockIdx.x * blockDim.x + threadIdx.x;
    const float* W; uint32_t *H, *L; int idx;
    if (i < W1W) { W = W1f; H = w1h; L = w1l; idx = i; }
    else if (i < W1W + W2W) { W = W2f; H = w2h; L = w2l; idx = i - W1W; }
    else if (i < W1W + W2W + W3W) { W = W3f; H = w3h; L = w3l; idx = i - W1W - W2W; }
    else return;
    uint32_t h, l;
    split2(W[2 * idx], W[2 * idx + 1], h, l);
    H[idx] = h; L[idx] = l;
}

// ---------------- KNN + interpolation + concat (exact fp32 op-tree, R8 form) ------------
// grid: (NY/256, BATCH), block 256, one y-point per thread
#define NXC 2048
__global__ __launch_bounds__(256)
void knn_interp_kernel(const float* __restrict__ yp, const float* __restrict__ yf,
                       const float* __restrict__ xp, const float* __restrict__ xf,
                       float* __restrict__ feat)
{
    __shared__ float4 s_pt[NXC];
    int b = blockIdx.y;
    int tid = threadIdx.x;
    int n = blockIdx.x * 256 + tid;
    int m = b * NY + n;

    const float* xpb = xp + (size_t)b * NX * 3;
    float px = yp[(size_t)m * 3 + 0];
    float py = yp[(size_t)m * 3 + 1];
    float pz = yp[(size_t)m * 3 + 2];
    float psq = __fadd_rn(__fadd_rn(__fmul_rn(px, px), __fmul_rn(py, py)),
                          __fmul_rn(pz, pz));

    float d0 = 3.4e38f, d1 = 3.4e38f, d2 = 3.4e38f;
    int i0 = 0, i1 = 0, i2 = 0;

    for (int ch = 0; ch < NX; ch += NXC) {
        __syncthreads();
        for (int j = tid; j < NXC; j += 256) {
            const float* xq = xpb + 3 * (size_t)(ch + j);
            float x = xq[0], y = xq[1], z = xq[2];
            float xsq = __fadd_rn(__fadd_rn(__fmul_rn(x, x), __fmul_rn(y, y)),
                                  __fmul_rn(z, z));
            s_pt[j] = make_float4(x, y, z, xsq);
        }
        __syncthreads();
        #pragma unroll 8
        for (int j = 0; j < NXC; j++) {
            float4 q = s_pt[j];
            float dot = __fmaf_rn(pz, q.z, __fmaf_rn(py, q.y, __fmul_rn(px, q.x)));
            float d = __fsub_rn(__fadd_rn(psq, q.w), __fmul_rn(2.0f, dot));
            if (d < d2) {
                int jj = ch + j;
                if (d < d1) {
                    d2 = d1; i2 = i1;
                    if (d < d0) { d1 = d0; i1 = i0; d0 = d; i0 = jj; }
                    else        { d1 = d;  i1 = jj; }
                } else { d2 = d; i2 = jj; }
            }
        }
    }

    float w0 = 1.0f / (d0 + IEPS);
    float w1 = 1.0f / (d1 + IEPS);
    float w2 = 1.0f / (d2 + IEPS);
    float ws = 1.0f / (w0 + w1 + w2);
    w0 *= ws; w1 *= ws; w2 *= ws;

    int lane = tid & 31;
    const float* xfb = xf + (size_t)b * NX * CX;
    unsigned mask = 0xffffffffu;
    for (int s = 0; s < 32; s++) {
        int   j0 = __shfl_sync(mask, i0, s);
        int   j1 = __shfl_sync(mask, i1, s);
        int   j2 = __shfl_sync(mask, i2, s);
        float a0 = __shfl_sync(mask, w0, s);
        float a1 = __shfl_sync(mask, w1, s);
        float a2 = __shfl_sync(mask, w2, s);
        int ms = m - lane + s;
        float* frow = feat + (size_t)ms * DIMF;
        const float4* ysrc = (const float4*)(yf + (size_t)ms * CY);
        ((float4*)frow)[lane] = ysrc[lane];
        const float4* r0 = (const float4*)(xfb + (size_t)j0 * CX);
        const float4* r1 = (const float4*)(xfb + (size_t)j1 * CX);
        const float4* r2 = (const float4*)(xfb + (size_t)j2 * CX);
        float4* dst = (float4*)(frow + CY);
        #pragma unroll
        for (int h = 0; h < 2; h++) {
            int c4 = h * 32 + lane;
            float4 v0 = r0[c4], v1 = r1[c4], v2 = r2[c4];
            float4 o;
            o.x = a0 * v0.x + a1 * v1.x + a2 * v2.x;
            o.y = a0 * v0.y + a1 * v1.y + a2 * v2.y;
            o.z = a0 * v0.z + a1 * v1.z + a2 * v2.z;
            o.w = a0 * v0.w + a1 * v1.w + a2 * v2.w;
            dst[c4] = o;
        }
    }
}

// ---------------- mma.sync 3xBF16 GEMM + fused BN stats (R8 config, 2 CTAs/SM) ---------
// Block tile 128x128x16, 8 warps (2m x 4n), warp tile 64x32.
// A: fp32 (+optional affine/relu), split at STS. B: pre-split, cp.async copy.
#define SROW_W 12
#define A_W   (128 * SROW_W)             // 1536 words per operand array
#define OFF_AL A_W
#define OFF_BH (2 * A_W)
#define OFF_BL (3 * A_W)
#define BUFF_W (4 * A_W)                 // 6144 words per buffer
#define GEMM_SMEM (2 * BUFF_W * 4)       // 49152 bytes

template<bool NORM>
__global__ __launch_bounds__(256, 2)
void mma_gemm_kernel(const float* __restrict__ Afp,
                     const uint32_t* __restrict__ BH, const uint32_t* __restrict__ BL,
                     const float* __restrict__ bias,
                     const float* __restrict__ scale, const float* __restrict__ shift,
                     float* __restrict__ Cmat,
                     float* __restrict__ gsum, float* __restrict__ gsq,
                     int Kdim, int Ndim)
{
    extern __shared__ uint32_t smw[];
    const uint32_t sbase = smem_u32(smw);
    const int tid = threadIdx.x;
    const int w = tid >> 5, lane = tid & 31;
    const int m0 = blockIdx.y * 128, n0 = blockIdx.x * 128;
    const int Kw = Kdim >> 1;

    const int aRow = tid >> 1;
    const int half = tid & 1;
    const int sOffA = aRow * SROW_W + half * 4;
    const float*    Ap  = Afp + (size_t)(m0 + aRow) * Kdim + half * 8;
    const uint32_t* BHp = BH + (size_t)(n0 + aRow) * Kw + half * 4;
    const uint32_t* BLp = BL + (size_t)(n0 + aRow) * Kw + half * 4;

    const int nch = Kdim >> 4;

    float acc[4][4][4];
    #pragma unroll
    for (int i = 0; i < 4; i++)
        #pragma unroll
        for (int j = 0; j < 4; j++)
            #pragma unroll
            for (int e = 0; e < 4; e++) acc[i][j][e] = 0.0f;

    float4 ra0, ra1;

    auto issueB = [&](int buf, int c) {
        CPASYNC16(sbase + 4u * (buf * BUFF_W + OFF_BH + sOffA), BHp + c * 8);
        CPASYNC16(sbase + 4u * (buf * BUFF_W + OFF_BL + sOffA), BLp + c * 8);
    };
    auto loadA = [&](int c) {
        ra0 = *(const float4*)(Ap + c * 16);
        ra1 = *(const float4*)(Ap + c * 16 + 4);
    };
    auto storeA = [&](int buf, int kc) {
        uint32_t* S = smw + buf * BUFF_W;
        float av[8] = {ra0.x, ra0.y, ra0.z, ra0.w, ra1.x, ra1.y, ra1.z, ra1.w};
        if (NORM) {
            const float* scp = scale + kc * 16 + half * 8;
            const float* shp = shift + kc * 16 + half * 8;
            #pragma unroll
            for (int j = 0; j < 8; j++)
                av[j] = fmaxf(fmaf(scp[j], av[j], shp[j]), 0.0f);
        }
        uint32_t hw[4], lw[4];
        #pragma unroll
        for (int p = 0; p < 4; p++) split2(av[2 * p], av[2 * p + 1], hw[p], lw[p]);
        *(uint4*)(S + sOffA)          = make_uint4(hw[0], hw[1], hw[2], hw[3]);
        *(uint4*)(S + OFF_AL + sOffA) = make_uint4(lw[0], lw[1], lw[2], lw[3]);
    };

    issueB(0, 0);
    loadA(0);
    storeA(0, 0);
    CPCOMMIT();
    CPWAIT0();
    __syncthreads();

    const int mtb = (w & 1) * 64;
    const int ntb = (w >> 1) * 32;
    const int fr = lane >> 2;
    const int fc = lane & 3;

    const int rA = mtb + ((lane >> 3) & 1) * 8 + (lane & 7);
    const int wA = (lane >> 4) * 4;
    const int rB = ntb + (lane >> 4) * 8 + (lane & 7);
    const int wB = ((lane >> 3) & 1) * 4;

    for (int c = 0; c < nch; c++) {
        const int buf = c & 1;
        const uint32_t soff = sbase + 4u * (buf * BUFF_W);
        if (c + 1 < nch) {
            issueB(buf ^ 1, c + 1);
            CPCOMMIT();
            loadA(c + 1);
        }

        uint32_t aF[4][4], bF[4][2];
        // A-hi
        #pragma unroll
        for (int i = 0; i < 4; i++) {
            uint32_t ad = soff + 4u * ((uint32_t)(rA + i * 16) * SROW_W + wA);
            LDSM4(aF[i][0], aF[i][1], aF[i][2], aF[i][3], ad);
        }
        // B-hi
        #pragma unroll
        for (int j2 = 0; j2 < 2; j2++) {
            uint32_t ad = soff + 4u * (OFF_BH + (uint32_t)(rB + j2 * 16) * SROW_W + wB);
            LDSM4(bF[2 * j2][0], bF[2 * j2][1], bF[2 * j2 + 1][0], bF[2 * j2 + 1][1], ad);
        }
        #pragma unroll
        for (int i = 0; i < 4; i++)
            #pragma unroll
            for (int j = 0; j < 4; j++)
                mma16(acc[i][j], aF[i], bF[j]);
        // B-lo (A-hi resident)
        #pragma unroll
        for (int j2 = 0; j2 < 2; j2++) {
            uint32_t ad = soff + 4u * (OFF_BL + (uint32_t)(rB + j2 * 16) * SROW_W + wB);
            LDSM4(bF[2 * j2][0], bF[2 * j2][1], bF[2 * j2 + 1][0], bF[2 * j2 + 1][1], ad);
        }
        #pragma unroll
        for (int i = 0; i < 4; i++)
            #pragma unroll
            for (int j = 0; j < 4; j++)
                mma16(acc[i][j], aF[i], bF[j]);
        // A-lo x B-hi
        #pragma unroll
        for (int i = 0; i < 4; i++) {
            uint32_t ad = soff + 4u * (OFF_AL + (uint32_t)(rA + i * 16) * SROW_W + wA);
            LDSM4(aF[i][0], aF[i][1], aF[i][2], aF[i][3], ad);
        }
        #pragma unroll
        for (int j2 = 0; j2 < 2; j2++) {
            uint32_t ad = soff + 4u * (OFF_BH + (uint32_t)(rB + j2 * 16) * SROW_W + wB);
            LDSM4(bF[2 * j2][0], bF[2 * j2][1], bF[2 * j2 + 1][0], bF[2 * j2 + 1][1], ad);
        }
        #pragma unroll
        for (int i = 0; i < 4; i++)
            #pragma unroll
            for (int j = 0; j < 4; j++)
                mma16(acc[i][j], aF[i], bF[j]);

        if (c + 1 < nch) {
            storeA(buf ^ 1, c + 1);
            CPWAIT0();
        }
        __syncthreads();
    }

    // Epilogue: write C (+bias) and accumulate per-column sum/sumsq.
    const int er = m0 + mtb + fr;
    const int ec = n0 + ntb + fc * 2;
    #pragma unroll
    for (int j = 0; j < 4; j++) {
        int cc = ec + j * 8;
        float2 b2 = *(const float2*)(bias + cc);
        float s0 = 0.f, s1 = 0.f, q0 = 0.f, q1 = 0.f;
        #pragma unroll
        for (int i = 0; i < 4; i++) {
            int r = er + i * 16;
            float o00 = acc[i][j][0] + b2.x, o01 = acc[i][j][1] + b2.y;
            float o10 = acc[i][j][2] + b2.x, o11 = acc[i][j][3] + b2.y;
            *(float2*)(Cmat + (size_t)r * Ndim + cc)       = make_float2(o00, o01);
            *(float2*)(Cmat + (size_t)(r + 8) * Ndim + cc) = make_float2(o10, o11);
            s0 += o00 + o10; s1 += o01 + o11;
            q0 += o00 * o00 + o10 * o10;
            q1 += o01 * o01 + o11 * o11;
        }
        #pragma unroll
        for (int off = 4; off < 32; off <<= 1) {
            s0 += __shfl_xor_sync(0xffffffffu, s0, off);
            s1 += __shfl_xor_sync(0xffffffffu, s1, off);
            q0 += __shfl_xor_sync(0xffffffffu, q0, off);
            q1 += __shfl_xor_sync(0xffffffffu, q1, off);
        }
        if (fr == 0) {
            atomicAdd(&gsum[cc], s0);
            atomicAdd(&gsum[cc + 1], s1);
            atomicAdd(&gsq[cc], q0);
            atomicAdd(&gsq[cc + 1], q1);
        }
    }
}

// ---------------- finalize BN affine (self-zeroing accumulators) ----------------
__global__ void finalize_kernel(float* __restrict__ sum, float* __restrict__ sq,
                                const float* __restrict__ g, const float* __restrict__ be,
                                float* __restrict__ scale, float* __restrict__ shift, int Cdim)
{
    int c = blockIdx.x * blockDim.x + threadIdx.x;
    if (c < Cdim) {
        const float invM = 1.0f / (float)MTOT;
        float mean = sum[c] * invM;
        float var  = sq[c] * invM - mean * mean;
        float inv  = rsqrtf(var + BN_EPS);
        float sc   = g[c] * inv;
        scale[c] = sc;
        shift[c] = be[c] - mean * sc;
        sum[c] = 0.0f;   // reset for next replay
        sq[c]  = 0.0f;
    }
}

// ---------------- final: normalize+relu layer3 and transpose to [B, C3, NY] ----------------
__global__ __launch_bounds__(256)
void trans_norm_kernel(const float* __restrict__ z3, const float* __restrict__ sc,
                       const float* __restrict__ sh, float* __restrict__ out)
{
    __shared__ float tile[32][33];
    int m0 = blockIdx.x * 32;
    int c0 = blockIdx.y * 32;
    int tx = threadIdx.x, ty = threadIdx.y;
    #pragma unroll
    for (int r = ty; r < 32; r += 8) {
        int c = c0 + tx;
        float v = z3[(size_t)(m0 + r) * C3 + c];
        v = fmaxf(fmaf(sc[c], v, sh[c]), 0.0f);
        tile[r][tx] = v;
    }
    __syncthreads();
    int b = m0 / NY;
    int n0 = m0 - b * NY;
    #pragma unroll
    for (int r = ty; r < 32; r += 8) {
        out[((size_t)b * C3 + c0 + r) * NY + n0 + tx] = tile[tx][r];
    }
}

// ---------------- launch ----------------
extern "C" void kernel_launch(void* const* d_in, const int* in_sizes, int n_in,
                              void* d_out, int out_size)
{
    const float* y_points = (const float*)d_in[0];
    const float* y_feats  = (const float*)d_in[1];
    const float* x_points = (const float*)d_in[2];
    const float* x_feats  = (const float*)d_in[3];
    const float* W1 = (const float*)d_in[4];
    const float* b1 = (const float*)d_in[5];
    const float* g1 = (const float*)d_in[6];
    const float* be1 = (const float*)d_in[7];
    const float* W2 = (const float*)d_in[8];
    const float* b2 = (const float*)d_in[9];
    const float* g2 = (const float*)d_in[10];
    const float* be2 = (const float*)d_in[11];
    const float* W3 = (const float*)d_in[12];
    const float* b3 = (const float*)d_in[13];
    const float* g3 = (const float*)d_in[14];
    const float* be3 = (const float*)d_in[15];
    float* out = (float*)d_out;

    float *feat, *z1, *z2, *z3, *red, *aff;
    uint32_t *w1h, *w1l, *w2h, *w2l, *w3h, *w3l;
    cudaGetSymbolAddress((void**)&feat, g_feat);
    cudaGetSymbolAddress((void**)&z1, g_z1);
    cudaGetSymbolAddress((void**)&z2, g_z2);
    cudaGetSymbolAddress((void**)&z3, g_z3);
    cudaGetSymbolAddress((void**)&red, g_red);
    cudaGetSymbolAddress((void**)&aff, g_aff);
    cudaGetSymbolAddress((void**)&w1h, g_w1h);
    cudaGetSymbolAddress((void**)&w1l, g_w1l);
    cudaGetSymbolAddress((void**)&w2h, g_w2h);
    cudaGetSymbolAddress((void**)&w2l, g_w2l);
    cudaGetSymbolAddress((void**)&w3h, g_w3h);
    cudaGetSymbolAddress((void**)&w3l, g_w3l);

    float* sum1 = red + 0;    float* sq1 = red + 512;
    float* sum2 = red + 1024; float* sq2 = red + 1280;
    float* sum3 = red + 1536; float* sq3 = red + 1664;
    float* sc1 = aff + 0;     float* sh1 = aff + 512;
    float* sc2 = aff + 1024;  float* sh2 = aff + 1280;
    float* sc3 = aff + 1536;  float* sh3 = aff + 1664;

    cudaFuncSetAttribute(mma_gemm_kernel<false>, cudaFuncAttributeMaxDynamicSharedMemorySize, GEMM_SMEM);
    cudaFuncSetAttribute(mma_gemm_kernel<true>,  cudaFuncAttributeMaxDynamicSharedMemorySize, GEMM_SMEM);

    split_w_all_kernel<<<(W1W + W2W + W3W + 255) / 256, 256>>>(
        W1, W2, W3, w1h, w1l, w2h, w2l, w3h, w3l);

    knn_interp_kernel<<<dim3(NY / 256, BATCH), 256>>>(y_points, y_feats, x_points, x_feats, feat);

    mma_gemm_kernel<false><<<dim3(C1 / 128, MTOT / 128), 256, GEMM_SMEM>>>(
        feat, w1h, w1l, b1, nullptr, nullptr, z1, sum1, sq1, DIMF, C1);
    finalize_kernel<<<2, 256>>>(sum1, sq1, g1, be1, sc1, sh1, C1);

    mma_gemm_kernel<true><<<dim3(C2 / 128, MTOT / 128), 256, GEMM_SMEM>>>(
        z1, w2h, w2l, b2, sc1, sh1, z2, sum2, sq2, C1, C2);
    finalize_kernel<<<1, 256>>>(sum2, sq2, g2, be2, sc2, sh2, C2);

    mma_gemm_kernel<true><<<dim3(C3 / 128, MTOT / 128), 256, GEMM_SMEM>>>(
        z2, w3h, w3l, b3, sc2, sh2, z3, sum3, sq3, C2, C3);
    finalize_kernel<<<1, 128>>>(sum3, sq3, g3, be3, sc3, sh3, C3);

    trans_norm_kernel<<<dim3(MTOT / 32, C3 / 32), dim3(32, 8)>>>(z3, sc3, sh3, out);
}

// round 16
// speedup vs baseline: 1.6063x; 1.0969x over previous
#include <cuda_runtime.h>
#include <cuda_fp16.h>
#include <cstdint>

// Problem constants
#define BATCH 4
#define NY 16384
#define NX 4096
#define CY 128
#define CX 256
#define DIMF 384       // CY + CX
#define C1 512
#define C2 256
#define C3 128
#define MTOT (BATCH*NY)   // 65536
#define IEPS 1e-8f
#define BN_EPS 1e-5f

// ---------------- scratch (device globals; no runtime alloc) ----------------
__device__ float g_feat[(size_t)MTOT * DIMF];
__device__ float g_z1[(size_t)MTOT * C1];
__device__ float g_z2[(size_t)MTOT * C2];
__device__ float g_z3[(size_t)MTOT * C3];
__device__ float g_red[1792];   // zero at load; finalize self-zeroes for replays
__device__ float g_aff[1792];
// pre-split weights (fp16x2 words, row-major [N][K/2])
#define W1W (C1 * DIMF / 2)
#define W2W (C2 * C1 / 2)
#define W3W (C3 * C2 / 2)
__device__ uint32_t g_w1h[W1W], g_w1l[W1W];
__device__ uint32_t g_w2h[W2W], g_w2l[W2W];
__device__ uint32_t g_w3h[W3W], g_w3l[W3W];

// pack two floats to fp16x2 (a -> low half, b -> high half)
__device__ __forceinline__ uint32_t cvt2h(float a, float b) {
    uint32_t r;
    asm("cvt.rn.f16x2.f32 %0, %1, %2;" : "=r"(r) : "f"(b), "f"(a));
    return r;
}
// split pair into fp16 hi word + fp16 residual word
__device__ __forceinline__ void split2h(float a, float b, uint32_t& h, uint32_t& l) {
    h = cvt2h(a, b);
    __half2 hh = *reinterpret_cast<__half2*>(&h);
    float h0 = __low2float(hh);
    float h1 = __high2float(hh);
    l = cvt2h(a - h0, b - h1);
}

// m16n8k16 FP16 mma (fp32 accumulate)
__device__ __forceinline__ void mma16(float* c, const uint32_t* a, const uint32_t* b) {
    asm volatile(
        "mma.sync.aligned.m16n8k16.row.col.f32.f16.f16.f32 "
        "{%0,%1,%2,%3}, {%4,%5,%6,%7}, {%8,%9}, {%0,%1,%2,%3};"
        : "+f"(c[0]), "+f"(c[1]), "+f"(c[2]), "+f"(c[3])
        : "r"(a[0]), "r"(a[1]), "r"(a[2]), "r"(a[3]),
          "r"(b[0]), "r"(b[1]));
}
#define LDSM4(r0, r1, r2, r3, addr) \
    asm volatile("ldmatrix.sync.aligned.m8n8.x4.shared.b16 {%0,%1,%2,%3}, [%4];" \
        : "=r"(r0), "=r"(r1), "=r"(r2), "=r"(r3) : "r"(addr))
#define CPASYNC16(dst, src) \
    asm volatile("cp.async.cg.shared.global [%0], [%1], 16;" :: "r"(dst), "l"(src))
#define CPCOMMIT()  asm volatile("cp.async.commit_group;" ::: "memory")
#define CPWAIT0()   asm volatile("cp.async.wait_group 0;" ::: "memory")

__device__ __forceinline__ uint32_t smem_u32(const void* p) {
    uint32_t a;
    asm("{ .reg .u64 t; cvta.to.shared.u64 t, %1; cvt.u32.u64 %0, t; }" : "=r"(a) : "l"(p));
    return a;
}

// ---------------- combined weight split prep (one launch) ----------------
__global__ void split_w_all_kernel(const float* __restrict__ W1f, const float* __restrict__ W2f,
                                   const float* __restrict__ W3f,
                                   uint32_t* __restrict__ w1h, uint32_t* __restrict__ w1l,
                                   uint32_t* __restrict__ w2h, uint32_t* __restrict__ w2l,
                                   uint32_t* __restrict__ w3h, uint32_t* __restrict__ w3l)
{
    int i = blockIdx.x * blockDim.x + threadIdx.x;
    const float* W; uint32_t *H, *L; int idx;
    if (i < W1W) { W = W1f; H = w1h; L = w1l; idx = i; }
    else if (i < W1W + W2W) { W = W2f; H = w2h; L = w2l; idx = i - W1W; }
    else if (i < W1W + W2W + W3W) { W = W3f; H = w3h; L = w3l; idx = i - W1W - W2W; }
    else return;
    uint32_t h, l;
    split2h(W[2 * idx], W[2 * idx + 1], h, l);
    H[idx] = h; L[idx] = l;
}

// ---------------- KNN + interpolation + concat (exact fp32 op-tree, R8 form) ------------
#define NXC 2048
__global__ __launch_bounds__(256)
void knn_interp_kernel(const float* __restrict__ yp, const float* __restrict__ yf,
                       const float* __restrict__ xp, const float* __restrict__ xf,
                       float* __restrict__ feat)
{
    __shared__ float4 s_pt[NXC];
    int b = blockIdx.y;
    int tid = threadIdx.x;
    int n = blockIdx.x * 256 + tid;
    int m = b * NY + n;

    const float* xpb = xp + (size_t)b * NX * 3;
    float px = yp[(size_t)m * 3 + 0];
    float py = yp[(size_t)m * 3 + 1];
    float pz = yp[(size_t)m * 3 + 2];
    float psq = __fadd_rn(__fadd_rn(__fmul_rn(px, px), __fmul_rn(py, py)),
                          __fmul_rn(pz, pz));

    float d0 = 3.4e38f, d1 = 3.4e38f, d2 = 3.4e38f;
    int i0 = 0, i1 = 0, i2 = 0;

    for (int ch = 0; ch < NX; ch += NXC) {
        __syncthreads();
        for (int j = tid; j < NXC; j += 256) {
            const float* xq = xpb + 3 * (size_t)(ch + j);
            float x = xq[0], y = xq[1], z = xq[2];
            float xsq = __fadd_rn(__fadd_rn(__fmul_rn(x, x), __fmul_rn(y, y)),
                                  __fmul_rn(z, z));
            s_pt[j] = make_float4(x, y, z, xsq);
        }
        __syncthreads();
        #pragma unroll 8
        for (int j = 0; j < NXC; j++) {
            float4 q = s_pt[j];
            float dot = __fmaf_rn(pz, q.z, __fmaf_rn(py, q.y, __fmul_rn(px, q.x)));
            float d = __fsub_rn(__fadd_rn(psq, q.w), __fmul_rn(2.0f, dot));
            if (d < d2) {
                int jj = ch + j;
                if (d < d1) {
                    d2 = d1; i2 = i1;
                    if (d < d0) { d1 = d0; i1 = i0; d0 = d; i0 = jj; }
                    else        { d1 = d;  i1 = jj; }
                } else { d2 = d; i2 = jj; }
            }
        }
    }

    float w0 = 1.0f / (d0 + IEPS);
    float w1 = 1.0f / (d1 + IEPS);
    float w2 = 1.0f / (d2 + IEPS);
    float ws = 1.0f / (w0 + w1 + w2);
    w0 *= ws; w1 *= ws; w2 *= ws;

    int lane = tid & 31;
    const float* xfb = xf + (size_t)b * NX * CX;
    unsigned mask = 0xffffffffu;
    for (int s = 0; s < 32; s++) {
        int   j0 = __shfl_sync(mask, i0, s);
        int   j1 = __shfl_sync(mask, i1, s);
        int   j2 = __shfl_sync(mask, i2, s);
        float a0 = __shfl_sync(mask, w0, s);
        float a1 = __shfl_sync(mask, w1, s);
        float a2 = __shfl_sync(mask, w2, s);
        int ms = m - lane + s;
        float* frow = feat + (size_t)ms * DIMF;
        const float4* ysrc = (const float4*)(yf + (size_t)ms * CY);
        ((float4*)frow)[lane] = ysrc[lane];
        const float4* r0 = (const float4*)(xfb + (size_t)j0 * CX);
        const float4* r1 = (const float4*)(xfb + (size_t)j1 * CX);
        const float4* r2 = (const float4*)(xfb + (size_t)j2 * CX);
        float4* dst = (float4*)(frow + CY);
        #pragma unroll
        for (int h = 0; h < 2; h++) {
            int c4 = h * 32 + lane;
            float4 v0 = r0[c4], v1 = r1[c4], v2 = r2[c4];
            float4 o;
            o.x = a0 * v0.x + a1 * v1.x + a2 * v2.x;
            o.y = a0 * v0.y + a1 * v1.y + a2 * v2.y;
            o.z = a0 * v0.z + a1 * v1.z + a2 * v2.z;
            o.w = a0 * v0.w + a1 * v1.w + a2 * v2.w;
            dst[c4] = o;
        }
    }
}

// ---------------- mma.sync 2xFP16 GEMM + fused BN stats ----------------
// D = fp16(A) @ (Bh + Bl)^T : 2 tensor products; B pre-split offline in fp16.
// Block tile 128x128x16, 8 warps (2m x 4n), warp tile 64x32.
// SMEM per buffer: Af[128][12] Bh[128][12] Bl[128][12] words -> 18KB; double buffered.
#define SROW_W 12
#define A_W   (128 * SROW_W)             // 1536 words per operand array
#define OFF_BH A_W
#define OFF_BL (2 * A_W)
#define BUFF_W (3 * A_W)                 // 4608 words per buffer
#define GEMM_SMEM (2 * BUFF_W * 4)       // 36864 bytes

template<bool NORM>
__global__ __launch_bounds__(256, 2)
void mma_gemm_kernel(const float* __restrict__ Afp,
                     const uint32_t* __restrict__ BH, const uint32_t* __restrict__ BL,
                     const float* __restrict__ bias,
                     const float* __restrict__ scale, const float* __restrict__ shift,
                     float* __restrict__ Cmat,
                     float* __restrict__ gsum, float* __restrict__ gsq,
                     int Kdim, int Ndim)
{
    extern __shared__ uint32_t smw[];
    const uint32_t sbase = smem_u32(smw);
    const int tid = threadIdx.x;
    const int w = tid >> 5, lane = tid & 31;
    const int m0 = blockIdx.y * 128, n0 = blockIdx.x * 128;
    const int Kw = Kdim >> 1;

    const int aRow = tid >> 1;
    const int half = tid & 1;
    const int sOffA = aRow * SROW_W + half * 4;
    const float*    Ap  = Afp + (size_t)(m0 + aRow) * Kdim + half * 8;
    const uint32_t* BHp = BH + (size_t)(n0 + aRow) * Kw + half * 4;
    const uint32_t* BLp = BL + (size_t)(n0 + aRow) * Kw + half * 4;

    const int nch = Kdim >> 4;

    float acc[4][4][4];
    #pragma unroll
    for (int i = 0; i < 4; i++)
        #pragma unroll
        for (int j = 0; j < 4; j++)
            #pragma unroll
            for (int e = 0; e < 4; e++) acc[i][j][e] = 0.0f;

    float4 ra0, ra1;

    auto issueB = [&](int buf, int c) {
        CPASYNC16(sbase + 4u * (buf * BUFF_W + OFF_BH + sOffA), BHp + c * 8);
        CPASYNC16(sbase + 4u * (buf * BUFF_W + OFF_BL + sOffA), BLp + c * 8);
    };
    auto loadA = [&](int c) {
        ra0 = *(const float4*)(Ap + c * 16);
        ra1 = *(const float4*)(Ap + c * 16 + 4);
    };
    auto storeA = [&](int buf, int kc) {
        uint32_t* S = smw + buf * BUFF_W;
        float av[8] = {ra0.x, ra0.y, ra0.z, ra0.w, ra1.x, ra1.y, ra1.z, ra1.w};
        if (NORM) {
            const float* scp = scale + kc * 16 + half * 8;
            const float* shp = shift + kc * 16 + half * 8;
            #pragma unroll
            for (int j = 0; j < 8; j++)
                av[j] = fmaxf(fmaf(scp[j], av[j], shp[j]), 0.0f);
        }
        uint32_t hw[4];
        #pragma unroll
        for (int p = 0; p < 4; p++) hw[p] = cvt2h(av[2 * p], av[2 * p + 1]);
        *(uint4*)(S + sOffA) = make_uint4(hw[0], hw[1], hw[2], hw[3]);
    };

    issueB(0, 0);
    loadA(0);
    storeA(0, 0);
    CPCOMMIT();
    CPWAIT0();
    __syncthreads();

    const int mtb = (w & 1) * 64;
    const int ntb = (w >> 1) * 32;
    const int fr = lane >> 2;
    const int fc = lane & 3;

    const int rA = mtb + ((lane >> 3) & 1) * 8 + (lane & 7);
    const int wA = (lane >> 4) * 4;
    const int rB = ntb + (lane >> 4) * 8 + (lane & 7);
    const int wB = ((lane >> 3) & 1) * 4;

    for (int c = 0; c < nch; c++) {
        const int buf = c & 1;
        const uint32_t soff = sbase + 4u * (buf * BUFF_W);
        if (c + 1 < nch) {
            issueB(buf ^ 1, c + 1);
            CPCOMMIT();
            loadA(c + 1);
        }

        uint32_t aF[4][4], bF[4][2];
        // A (fp16) fragments
        #pragma unroll
        for (int i = 0; i < 4; i++) {
            uint32_t ad = soff + 4u * ((uint32_t)(rA + i * 16) * SROW_W + wA);
            LDSM4(aF[i][0], aF[i][1], aF[i][2], aF[i][3], ad);
        }
        // B-hi
        #pragma unroll
        for (int j2 = 0; j2 < 2; j2++) {
            uint32_t ad = soff + 4u * (OFF_BH + (uint32_t)(rB + j2 * 16) * SROW_W + wB);
            LDSM4(bF[2 * j2][0], bF[2 * j2][1], bF[2 * j2 + 1][0], bF[2 * j2 + 1][1], ad);
        }
        #pragma unroll
        for (int i = 0; i < 4; i++)
            #pragma unroll
            for (int j = 0; j < 4; j++)
                mma16(acc[i][j], aF[i], bF[j]);
        // B-lo (A resident)
        #pragma unroll
        for (int j2 = 0; j2 < 2; j2++) {
            uint32_t ad = soff + 4u * (OFF_BL + (uint32_t)(rB + j2 * 16) * SROW_W + wB);
            LDSM4(bF[2 * j2][0], bF[2 * j2][1], bF[2 * j2 + 1][0], bF[2 * j2 + 1][1], ad);
        }
        #pragma unroll
        for (int i = 0; i < 4; i++)
            #pragma unroll
            for (int j = 0; j < 4; j++)
                mma16(acc[i][j], aF[i], bF[j]);

        if (c + 1 < nch) {
            storeA(buf ^ 1, c + 1);
            CPWAIT0();
        }
        __syncthreads();
    }

    // Epilogue: write C (+bias) and accumulate per-column sum/sumsq.
    const int er = m0 + mtb + fr;
    const int ec = n0 + ntb + fc * 2;
    #pragma unroll
    for (int j = 0; j < 4; j++) {
        int cc = ec + j * 8;
        float2 b2 = *(const float2*)(bias + cc);
        float s0 = 0.f, s1 = 0.f, q0 = 0.f, q1 = 0.f;
        #pragma unroll
        for (int i = 0; i < 4; i++) {
            int r = er + i * 16;
            float o00 = acc[i][j][0] + b2.x, o01 = acc[i][j][1] + b2.y;
            float o10 = acc[i][j][2] + b2.x, o11 = acc[i][j][3] + b2.y;
            *(float2*)(Cmat + (size_t)r * Ndim + cc)       = make_float2(o00, o01);
            *(float2*)(Cmat + (size_t)(r + 8) * Ndim + cc) = make_float2(o10, o11);
            s0 += o00 + o10; s1 += o01 + o11;
            q0 += o00 * o00 + o10 * o10;
            q1 += o01 * o01 + o11 * o11;
        }
        #pragma unroll
        for (int off = 4; off < 32; off <<= 1) {
            s0 += __shfl_xor_sync(0xffffffffu, s0, off);
            s1 += __shfl_xor_sync(0xffffffffu, s1, off);
            q0 += __shfl_xor_sync(0xffffffffu, q0, off);
            q1 += __shfl_xor_sync(0xffffffffu, q1, off);
        }
        if (fr == 0) {
            atomicAdd(&gsum[cc], s0);
            atomicAdd(&gsum[cc + 1], s1);
            atomicAdd(&gsq[cc], q0);
            atomicAdd(&gsq[cc + 1], q1);
        }
    }
}

// ---------------- finalize BN affine (self-zeroing accumulators) ----------------
__global__ void finalize_kernel(float* __restrict__ sum, float* __restrict__ sq,
                                const float* __restrict__ g, const float* __restrict__ be,
                                float* __restrict__ scale, float* __restrict__ shift, int Cdim)
{
    int c = blockIdx.x * blockDim.x + threadIdx.x;
    if (c < Cdim) {
        const float invM = 1.0f / (float)MTOT;
        float mean = sum[c] * invM;
        float var  = sq[c] * invM - mean * mean;
        float inv  = rsqrtf(var + BN_EPS);
        float sc   = g[c] * inv;
        scale[c] = sc;
        shift[c] = be[c] - mean * sc;
        sum[c] = 0.0f;   // reset for next replay
        sq[c]  = 0.0f;
    }
}

// ---------------- final: normalize+relu layer3 and transpose to [B, C3, NY] ----------------
__global__ __launch_bounds__(256)
void trans_norm_kernel(const float* __restrict__ z3, const float* __restrict__ sc,
                       const float* __restrict__ sh, float* __restrict__ out)
{
    __shared__ float tile[32][33];
    int m0 = blockIdx.x * 32;
    int c0 = blockIdx.y * 32;
    int tx = threadIdx.x, ty = threadIdx.y;
    #pragma unroll
    for (int r = ty; r < 32; r += 8) {
        int c = c0 + tx;
        float v = z3[(size_t)(m0 + r) * C3 + c];
        v = fmaxf(fmaf(sc[c], v, sh[c]), 0.0f);
        tile[r][tx] = v;
    }
    __syncthreads();
    int b = m0 / NY;
    int n0 = m0 - b * NY;
    #pragma unroll
    for (int r = ty; r < 32; r += 8) {
        out[((size_t)b * C3 + c0 + r) * NY + n0 + tx] = tile[tx][r];
    }
}

// ---------------- launch ----------------
extern "C" void kernel_launch(void* const* d_in, const int* in_sizes, int n_in,
                              void* d_out, int out_size)
{
    const float* y_points = (const float*)d_in[0];
    const float* y_feats  = (const float*)d_in[1];
    const float* x_points = (const float*)d_in[2];
    const float* x_feats  = (const float*)d_in[3];
    const float* W1 = (const float*)d_in[4];
    const float* b1 = (const float*)d_in[5];
    const float* g1 = (const float*)d_in[6];
    const float* be1 = (const float*)d_in[7];
    const float* W2 = (const float*)d_in[8];
    const float* b2 = (const float*)d_in[9];
    const float* g2 = (const float*)d_in[10];
    const float* be2 = (const float*)d_in[11];
    const float* W3 = (const float*)d_in[12];
    const float* b3 = (const float*)d_in[13];
    const float* g3 = (const float*)d_in[14];
    const float* be3 = (const float*)d_in[15];
    float* out = (float*)d_out;

    float *feat, *z1, *z2, *z3, *red, *aff;
    uint32_t *w1h, *w1l, *w2h, *w2l, *w3h, *w3l;
    cudaGetSymbolAddress((void**)&feat, g_feat);
    cudaGetSymbolAddress((void**)&z1, g_z1);
    cudaGetSymbolAddress((void**)&z2, g_z2);
    cudaGetSymbolAddress((void**)&z3, g_z3);
    cudaGetSymbolAddress((void**)&red, g_red);
    cudaGetSymbolAddress((void**)&aff, g_aff);
    cudaGetSymbolAddress((void**)&w1h, g_w1h);
    cudaGetSymbolAddress((void**)&w1l, g_w1l);
    cudaGetSymbolAddress((void**)&w2h, g_w2h);
    cudaGetSymbolAddress((void**)&w2l, g_w2l);
    cudaGetSymbolAddress((void**)&w3h, g_w3h);
    cudaGetSymbolAddress((void**)&w3l, g_w3l);

    float* sum1 = red + 0;    float* sq1 = red + 512;
    float* sum2 = red + 1024; float* sq2 = red + 1280;
    float* sum3 = red + 1536; float* sq3 = red + 1664;
    float* sc1 = aff + 0;     float* sh1 = aff + 512;
    float* sc2 = aff + 1024;  float* sh2 = aff + 1280;
    float* sc3 = aff + 1536;  float* sh3 = aff + 1664;

    cudaFuncSetAttribute(mma_gemm_kernel<false>, cudaFuncAttributeMaxDynamicSharedMemorySize, GEMM_SMEM);
    cudaFuncSetAttribute(mma_gemm_kernel<true>,  cudaFuncAttributeMaxDynamicSharedMemorySize, GEMM_SMEM);

    split_w_all_kernel<<<(W1W + W2W + W3W + 255) / 256, 256>>>(
        W1, W2, W3, w1h, w1l, w2h, w2l, w3h, w3l);

    knn_interp_kernel<<<dim3(NY / 256, BATCH), 256>>>(y_points, y_feats, x_points, x_feats, feat);

    mma_gemm_kernel<false><<<dim3(C1 / 128, MTOT / 128), 256, GEMM_SMEM>>>(
        feat, w1h, w1l, b1, nullptr, nullptr, z1, sum1, sq1, DIMF, C1);
    finalize_kernel<<<2, 256>>>(sum1, sq1, g1, be1, sc1, sh1, C1);

    mma_gemm_kernel<true><<<dim3(C2 / 128, MTOT / 128), 256, GEMM_SMEM>>>(
        z1, w2h, w2l, b2, sc1, sh1, z2, sum2, sq2, C1, C2);
    finalize_kernel<<<1, 256>>>(sum2, sq2, g2, be2, sc2, sh2, C2);

    mma_gemm_kernel<true><<<dim3(C3 / 128, MTOT / 128), 256, GEMM_SMEM>>>(
        z2, w3h, w3l, b3, sc2, sh2, z3, sum3, sq3, C2, C3);
    finalize_kernel<<<1, 128>>>(sum3, sq3, g3, be3, sc3, sh3, C3);

    trans_norm_kernel<<<dim3(MTOT / 32, C3 / 32), dim3(32, 8)>>>(z3, sc3, sh3, out);
}